// round 3
// baseline (speedup 1.0000x reference)
#include <cuda_runtime.h>
#include <cuda_bf16.h>

// KAN 3x3 conv, x in [0,1), uniform cubic B-spline (G=5, s=3, h=0.4).
// Spline per (p, k) is one cubic: f = c0 + c1 t + c2 t^2 + c3 t^3, t = frac(2.5x+0.5),
// k = floor(2.5x+0.5) in {0,1,2}. Coef table in GLOBAL memory, 64B-padded per p so a
// warp's k-divergent LDG.128 stays within one 128B line (1 l1tex wavefront).

#define OUT_H 254
#define OUT_W 254
#define IN_W  256
#define TW 32
#define TH 32          // block tile: 32x32 outputs
#define TY 4           // outputs per thread (column)
#define IW 34
#define IH 34

__device__ float4 g_coef4[9 * 4];   // [p*4 + k], k padded 3->4 (64B per p)

__global__ __launch_bounds__(256)
void kan_conv_kernel(const float* __restrict__ x,
                     const float* __restrict__ bw,
                     const float* __restrict__ sw,
                     float* __restrict__ out)
{
    __shared__ float2 s_pix[IH][IW];   // (u, silu)

    const int tx  = threadIdx.x;       // 0..31
    const int ty  = threadIdx.y;       // 0..7
    const int tid = ty * 32 + tx;
    const int b   = blockIdx.z;
    const int ox0 = blockIdx.x * TW;
    const int oy0 = blockIdx.y * TH;

    // ---- build coef table (every block writes identical values; visible to this
    // block after the fence+barrier; cross-block races write identical bits) ----
    if (tid < 27) {
        const int p = tid / 3;
        const int k = tid - 3 * p;
        const float* w = sw + p * 8 + (k + 2);
        const float w0 = __ldg(w + 0);
        const float w1 = __ldg(w + 1);
        const float w2 = __ldg(w + 2);
        const float w3 = __ldg(w + 3);
        float4 c;
        c.x = (w0 + 4.0f * w1 + w2) * (1.0f / 6.0f);
        c.y = (w2 - w0) * 0.5f;
        c.z = (w0 - 2.0f * w1 + w2) * 0.5f;
        c.w = (3.0f * (w1 - w2) + (w3 - w0)) * (1.0f / 6.0f);
        g_coef4[p * 4 + k] = c;
    }

    // ---- stage input tile: u = 2.5x+0.5 and silu(x), once per pixel ----
    const float* xb = x + (size_t)b * (IN_W * IN_W);
    #pragma unroll
    for (int idx = tid; idx < IW * IH; idx += 256) {
        const int r = idx / IW;
        const int c = idx - r * IW;
        const int gy = min(oy0 + r, IN_W - 1);
        const int gx = min(ox0 + c, IN_W - 1);
        const float v = __ldg(xb + gy * IN_W + gx);
        const float u = 2.5f * v + 0.5f;
        const float e = __expf(-v);
        const float sil = __fdividef(v, 1.0f + e);
        s_pix[r][c] = make_float2(u, sil);
    }
    __threadfence_block();
    __syncthreads();

    // base weights in registers (uniform LDG, L1-hot)
    float bwr[9];
    #pragma unroll
    for (int p = 0; p < 9; p++) bwr[p] = __ldg(bw + p);

    const int ox = ox0 + tx;
    const int oyb = oy0 + ty * TY;

    float acc[TY];
    #pragma unroll
    for (int j = 0; j < TY; j++) acc[j] = 0.0f;

    // rolling over 6 input rows; each pixel read+decoded once, feeds up to 3 accs
    #pragma unroll
    for (int r = 0; r < TY + 2; r++) {
        #pragma unroll
        for (int dx = 0; dx < 3; dx++) {
            const float2 pv = s_pix[ty * TY + r][tx + dx];
            const float u   = pv.x;
            const float sil = pv.y;
            int k = (int)u;            // u in [0.5, 3): trunc == floor
            k = min(k, 2);
            const float t  = u - (float)k;
            const float t2 = t * t;
            const float t3 = t2 * t;
            // output j receives this pixel with dy = r - j, valid j in [r-2, r]
            #pragma unroll
            for (int j = 0; j < TY; j++) {
                const int dy = r - j;
                if (dy < 0 || dy > 2) continue;   // compile-time pruned
                const int p = dy * 3 + dx;
                const float4 c = g_coef4[p * 4 + k];   // LDG.128, 1 line/warp
                float a = acc[j];
                a += c.x;
                a = fmaf(c.y, t,  a);
                a = fmaf(c.z, t2, a);
                a = fmaf(c.w, t3, a);
                a = fmaf(sil, bwr[p], a);
                acc[j] = a;
            }
        }
    }

    if (ox < OUT_W) {
        float* ob = out + (size_t)b * (OUT_H * OUT_W) + ox;
        #pragma unroll
        for (int j = 0; j < TY; j++) {
            const int oy = oyb + j;
            if (oy < OUT_H) ob[oy * OUT_W] = acc[j];
        }
    }
}

extern "C" void kernel_launch(void* const* d_in, const int* in_sizes, int n_in,
                              void* d_out, int out_size) {
    const float* x  = (const float*)d_in[0];
    const float* bw = (const float*)d_in[1];
    const float* sw = (const float*)d_in[2];
    float* out = (float*)d_out;

    dim3 block(32, 8, 1);
    dim3 grid((OUT_W + TW - 1) / TW,   // 8
              (OUT_H + TH - 1) / TH,   // 8
              32);                     // batch
    kan_conv_kernel<<<grid, block>>>(x, bw, sw, out);
}